// round 10
// baseline (speedup 1.0000x reference)
#include <cuda_runtime.h>
#include <math.h>

#define HH 512
#define WW 512

typedef unsigned long long ull;

// ---------- packed f32x2 primitives (Blackwell sm_100+) ----------
__device__ __forceinline__ ull PK2(float lo, float hi){
    ull d; asm("mov.b64 %0, {%1, %2};" : "=l"(d)
               : "r"(__float_as_uint(lo)), "r"(__float_as_uint(hi)));
    return d;
}
__device__ __forceinline__ void UPK2(float& lo, float& hi, ull d){
    unsigned a, b; asm("mov.b64 {%0, %1}, %2;" : "=r"(a), "=r"(b) : "l"(d));
    lo = __uint_as_float(a); hi = __uint_as_float(b);
}
__device__ __forceinline__ ull ADD2(ull a, ull b){
    ull d; asm("add.rn.f32x2 %0, %1, %2;" : "=l"(d) : "l"(a), "l"(b)); return d;
}
__device__ __forceinline__ ull MUL2(ull a, ull b){
    ull d; asm("mul.rn.f32x2 %0, %1, %2;" : "=l"(d) : "l"(a), "l"(b)); return d;
}
__device__ __forceinline__ ull FMA2(ull a, ull b, ull c){
    ull d; asm("fma.rn.f32x2 %0, %1, %2, %3;" : "=l"(d) : "l"(a), "l"(b), "l"(c)); return d;
}
#define BC(c) PK2(c, c)
// exact negation: flip both sign bits (ALU pipe, not FMA)
__device__ __forceinline__ ull NEGX(ull a){ return a ^ 0x8000000080000000ULL; }
// a - b  (exact)
__device__ __forceinline__ ull SUB2(ull a, ull b){ return ADD2(a, NEGX(b)); }

// cos(k*pi/16)
#define P1 0.980785280403230449f
#define P2 0.923879532511286756f
#define P3 0.831469612302545237f
#define P4 0.707106781186547524f
#define P5 0.555570233019602225f
#define P6 0.382683432365089772f
#define P7 0.195090322016128268f

__constant__ float gQY[64] = {
  16,11,10,16,24,40,51,61,
  12,12,14,19,26,58,60,55,
  14,13,16,24,40,57,69,56,
  14,17,22,29,51,87,80,62,
  18,22,37,56,68,109,103,77,
  24,35,55,64,81,104,113,92,
  49,64,78,87,103,121,120,101,
  72,92,95,98,112,100,103,99
};
__constant__ float gQC[64] = {
  17,18,24,47,99,99,99,99,
  18,21,26,66,99,99,99,99,
  24,26,56,99,99,99,99,99,
  47,66,99,99,99,99,99,99,
  99,99,99,99,99,99,99,99,
  99,99,99,99,99,99,99,99,
  99,99,99,99,99,99,99,99,
  99,99,99,99,99,99,99,99
};

// packed forward 8-pt DCT (butterfly form), lanes independent
__device__ __forceinline__ void fdct8p(const ull* d, ull* t)
{
    ull Pa=BC(P1), Pb=BC(P2), Pc=BC(P3), Pd=BC(P4), Pe=BC(P5), Pf=BC(P6), Pg=BC(P7);
    ull a0=ADD2(d[0],d[7]), a1=ADD2(d[1],d[6]), a2=ADD2(d[2],d[5]), a3=ADD2(d[3],d[4]);
    ull b0=SUB2(d[0],d[7]), b1=SUB2(d[1],d[6]), b2=SUB2(d[2],d[5]), b3=SUB2(d[3],d[4]);
    t[0]=ADD2(ADD2(a0,a1), ADD2(a2,a3));
    t[4]=MUL2(SUB2(ADD2(a0,a3), ADD2(a1,a2)), Pd);
    ull s03=SUB2(a0,a3), s12=SUB2(a1,a2);
    t[2]=FMA2(s03,Pb, MUL2(s12,Pf));
    t[6]=SUB2(MUL2(s03,Pf), MUL2(s12,Pb));
    t[1]=FMA2(b0,Pa, FMA2(b1,Pc, FMA2(b2,Pe, MUL2(b3,Pg))));
    t[3]=SUB2(MUL2(b0,Pc), FMA2(b1,Pg, FMA2(b2,Pa, MUL2(b3,Pe))));
    t[5]=SUB2(FMA2(b0,Pe, FMA2(b2,Pg, MUL2(b3,Pc))), MUL2(b1,Pa));
    t[7]=SUB2(FMA2(b0,Pg, MUL2(b2,Pc)), FMA2(b1,Pe, MUL2(b3,Pa)));
}

// packed inverse 8-pt DCT
__device__ __forceinline__ void idct8p(const ull* e, ull* s)
{
    ull Pa=BC(P1), Pb=BC(P2), Pc=BC(P3), Pd=BC(P4), Pe=BC(P5), Pf=BC(P6), Pg=BC(P7);
    ull p0 = ADD2(e[0], FMA2(e[2],Pb, FMA2(e[4],Pd, MUL2(e[6],Pf))));
    ull p1 = SUB2(FMA2(e[2],Pf, e[0]), FMA2(e[4],Pd, MUL2(e[6],Pb)));
    ull p2 = SUB2(FMA2(e[6],Pb, e[0]), FMA2(e[2],Pf, MUL2(e[4],Pd)));
    ull p3 = SUB2(FMA2(e[4],Pd, e[0]), FMA2(e[2],Pb, MUL2(e[6],Pf)));
    ull q0 = FMA2(e[1],Pa, FMA2(e[3],Pc, FMA2(e[5],Pe, MUL2(e[7],Pg))));
    ull q1 = SUB2(MUL2(e[1],Pc), FMA2(e[3],Pg, FMA2(e[5],Pa, MUL2(e[7],Pe))));
    ull q2 = SUB2(FMA2(e[1],Pe, FMA2(e[5],Pg, MUL2(e[7],Pc))), MUL2(e[3],Pa));
    ull q3 = SUB2(FMA2(e[1],Pg, MUL2(e[5],Pc)), FMA2(e[3],Pe, MUL2(e[7],Pa)));
    s[0]=ADD2(p0,q0); s[7]=SUB2(p0,q0);
    s[1]=ADD2(p1,q1); s[6]=SUB2(p1,q1);
    s[2]=ADD2(p2,q2); s[5]=SUB2(p2,q2);
    s[3]=ADD2(p3,q3); s[4]=SUB2(p3,q3);
}

// packed diff_round: z - (1/pi) sum_{n=1..9} ((-1)^{n+1}/n) sin(2 pi n z)
__device__ __forceinline__ ull dr2(ull z)
{
    ull MG = BC(12582912.0f);              // 1.5 * 2^23 round-to-nearest magic
    ull tr = ADD2(z, MG);
    ull w  = SUB2(tr, MG);                 // rint(z), exact (|z| << 2^22)
    ull r  = SUB2(z, w);                   // frac in [-0.5, 0.5], exact
    ull h  = MUL2(r, BC(3.14159265358979324f));
    ull h2 = MUL2(h, h);
    ull sp = FMA2(h2, FMA2(h2, FMA2(h2, FMA2(h2, BC(2.75573192e-6f), BC(-1.98412698e-4f)),
                     BC(8.33333333e-3f)), BC(-1.66666667e-1f)), BC(1.0f));
    ull sh = MUL2(h, sp);
    ull ch = FMA2(h2, FMA2(h2, FMA2(h2, FMA2(h2, BC(2.48015873e-5f), BC(-1.38888889e-3f)),
                     BC(4.16666667e-2f)), BC(-0.5f)), BC(1.0f));
    ull sa = MUL2(ADD2(sh, sh), ch);                    // sin(2 pi r)
    ull twoc = FMA2(MUL2(sh, BC(-4.0f)), sh, BC(2.0f)); // 2 cos(2 pi r)
    ull sb = MUL2(twoc, sa);                            // s2
    ull acc = FMA2(sb, BC(-0.159154943f), MUL2(sa, BC(0.318309886f)));
    ull sc;
    sc = FMA2(twoc, sb, NEGX(sa)); acc = FMA2(sc, BC( 0.106103295f ), acc); sa=sb; sb=sc;
    sc = FMA2(twoc, sb, NEGX(sa)); acc = FMA2(sc, BC(-0.0795774715f), acc); sa=sb; sb=sc;
    sc = FMA2(twoc, sb, NEGX(sa)); acc = FMA2(sc, BC( 0.0636619772f), acc); sa=sb; sb=sc;
    sc = FMA2(twoc, sb, NEGX(sa)); acc = FMA2(sc, BC(-0.0530516477f), acc); sa=sb; sb=sc;
    sc = FMA2(twoc, sb, NEGX(sa)); acc = FMA2(sc, BC( 0.0454728409f), acc); sa=sb; sb=sc;
    sc = FMA2(twoc, sb, NEGX(sa)); acc = FMA2(sc, BC(-0.0397887358f), acc); sa=sb; sb=sc;
    sc = FMA2(twoc, sb, NEGX(sa)); acc = FMA2(sc, BC( 0.0353677651f), acc);
    return SUB2(z, acc);
}

#define YST   68     // luma tile row stride (floats): 64 + 4 pad
#define CST   36     // pooled chroma row stride: 32 + 4 pad
#define SCRG  176    // scratch group stride (floats): 8 rows * 10 pairs + 8 pad

__global__ void __launch_bounds__(192, 4)
djpeg_kernel(const float* __restrict__ in, float* __restrict__ out)
{
    __shared__ __align__(16) float sY  [32*YST];     // luma 32x64
    __shared__ __align__(16) float sCbP[16*CST];     // pooled chroma in 16x32
    __shared__ __align__(16) float sCrP[16*CST];
    __shared__ __align__(16) float sCbO[16*CST];     // reconstructed chroma (-128)
    __shared__ __align__(16) float sCrO[16*CST];
    __shared__ __align__(16) float sScr[24*SCRG];    // pair transpose scratch
    __shared__ __align__(16) float sZT[2*64*2];      // packed quant multipliers
    __shared__ __align__(16) float sDT[2*64*2];      // packed dequant multipliers

    const int tid = threadIdx.x;
    const int b   = blockIdx.z;
    const int px0 = blockIdx.x * 64;
    const int py0 = blockIdx.y * 32;

    const float* base = in + (size_t)b * 3 * HH * WW;

    // ---- load + RGB->YCbCr + chroma pooling (256 tasks) -----------------
    for (int ti = tid; ti < 256; ti += 192) {
        int rp = ti >> 4;               // row-pair 0..15
        int c4 = (ti & 15) << 2;        // col offset 0,4,...,60
        size_t o0 = ((size_t)(py0 + 2*rp) * WW + px0 + c4) >> 2;
        const float4* R4 = (const float4*)base;
        const float4* G4 = (const float4*)(base + HH*WW);
        const float4* B4 = (const float4*)(base + 2*HH*WW);
        float4 Ra = R4[o0], Rb = R4[o0 + WW/4];
        float4 Ga = G4[o0], Gb = G4[o0 + WW/4];
        float4 Ba = B4[o0], Bb = B4[o0 + WW/4];
        float r0[4]={Ra.x,Ra.y,Ra.z,Ra.w}, r1[4]={Rb.x,Rb.y,Rb.z,Rb.w};
        float g0[4]={Ga.x,Ga.y,Ga.z,Ga.w}, g1[4]={Gb.x,Gb.y,Gb.z,Gb.w};
        float b0[4]={Ba.x,Ba.y,Ba.z,Ba.w}, b1[4]={Bb.x,Bb.y,Bb.z,Bb.w};

        float ya[4], yb[4];
        #pragma unroll
        for (int w = 0; w < 4; w++) {
            ya[w] = fmaf(76.245f, r0[w], fmaf(149.685f, g0[w], 29.07f * b0[w]));
            yb[w] = fmaf(76.245f, r1[w], fmaf(149.685f, g1[w], 29.07f * b1[w]));
        }
        *(float4*)(sY + (2*rp  )*YST + c4) = make_float4(ya[0],ya[1],ya[2],ya[3]);
        *(float4*)(sY + (2*rp+1)*YST + c4) = make_float4(yb[0],yb[1],yb[2],yb[3]);

        float cb[2], cr[2];
        #pragma unroll
        for (int q = 0; q < 2; q++) {
            float rs = (r0[2*q]+r0[2*q+1]) + (r1[2*q]+r1[2*q+1]);
            float gs = (g0[2*q]+g0[2*q+1]) + (g1[2*q]+g1[2*q+1]);
            float bs = (b0[2*q]+b0[2*q+1]) + (b1[2*q]+b1[2*q+1]);
            cb[q] = fmaf(-10.75692f, rs, fmaf(-21.11808f, gs, fmaf(31.875f,   bs, 128.0f)));
            cr[q] = fmaf( 31.875f,   rs, fmaf(-26.69136f, gs, fmaf(-5.18364f, bs, 128.0f)));
        }
        *(float2*)(sCbP + rp*CST + (c4 >> 1)) = make_float2(cb[0], cb[1]);
        *(float2*)(sCrP + rp*CST + (c4 >> 1)) = make_float2(cr[0], cr[1]);
    }
    if (tid >= 128) {                  // 64 threads build packed tables
        int i = tid - 128;             // 0..63
        int u = i & 7, v = i >> 3;
        float al = ((u==0)?0.70710678118654752f:1.0f) * ((v==0)?0.70710678118654752f:1.0f);
        float ty = gQY[i], tc = gQC[i];
        float zy = 2.5f   * al / ty,  dy = 0.025f * al * ty;
        float zc = 2.5f   * al / tc,  dc = 0.025f * al * tc;
        ((float2*)sZT)[i]      = make_float2(zy, zy);
        ((float2*)sZT)[64 + i] = make_float2(zc, zc);
        ((float2*)sDT)[i]      = make_float2(dy, dy);
        ((float2*)sDT)[64 + i] = make_float2(dc, dc);
    }
    __syncthreads();

    // ---- per-pair transforms: 24 groups of 8 threads, 2 blocks each -----
    const int g = tid >> 3;   // 0..15 Y pairs, 16..19 Cb pairs, 20..23 Cr pairs
    const int j = tid & 7;
    const bool isY = (g < 16);

    const float *pA, *pB;
    float *oA, *oB;
    if (isY) {
        int by = g >> 2, k = g & 3;
        float* r = sY + (by*8 + j)*YST + k*16;
        pA = r;      pB = r + 8;
        oA = r;      oB = r + 8;
    } else {
        int q  = g - 16;
        bool isCr = (q >= 4);
        int q2 = isCr ? q - 4 : q;
        int by = q2 >> 1, k = q2 & 1;
        int off = (by*8 + j)*CST + k*16;
        const float* src = (isCr ? sCrP : sCbP) + off;
        float*       dst = (isCr ? sCrO : sCbO) + off;
        pA = src;  pB = src + 8;
        oA = dst;  oB = dst + 8;
    }
    const ull* zt = (const ull*)sZT + (isY ? 0 : 64) + j*8;
    const ull* dt = (const ull*)sDT + (isY ? 0 : 64) + j*8;
    float* scrf = sScr + g*SCRG;

    ull d[8];
    {
        float4 A0 = *(const float4*)pA, A1 = *(const float4*)(pA + 4);
        float4 B0 = *(const float4*)pB, B1 = *(const float4*)(pB + 4);
        d[0]=PK2(A0.x,B0.x); d[1]=PK2(A0.y,B0.y); d[2]=PK2(A0.z,B0.z); d[3]=PK2(A0.w,B0.w);
        d[4]=PK2(A1.x,B1.x); d[5]=PK2(A1.y,B1.y); d[6]=PK2(A1.z,B1.z); d[7]=PK2(A1.w,B1.w);
    }

    // FWD pass 1 (-128 level shift folded into DC lane)
    ull t[8];
    fdct8p(d, t);
    t[0] = ADD2(t[0], BC(-1024.0f));

    #pragma unroll
    for (int v = 0; v < 8; v++) *(ull*)(scrf + (v*10 + j)*2) = t[v];
    __syncwarp();
    ull tr[8];
    {
        ulonglong2 u0 = *(const ulonglong2*)(scrf + j*20);
        ulonglong2 u1 = *(const ulonglong2*)(scrf + j*20 + 4);
        ulonglong2 u2 = *(const ulonglong2*)(scrf + j*20 + 8);
        ulonglong2 u3 = *(const ulonglong2*)(scrf + j*20 + 12);
        tr[0]=u0.x; tr[1]=u0.y; tr[2]=u1.x; tr[3]=u1.y;
        tr[4]=u2.x; tr[5]=u2.y; tr[6]=u3.x; tr[7]=u3.y;
    }
    __syncwarp();

    // FWD pass 2 + quant + diff_round + dequant (packed)
    ull t2[8];
    fdct8p(tr, t2);
    ull e[8];
    #pragma unroll
    for (int u = 0; u < 8; u++)
        e[u] = MUL2(dr2(MUL2(t2[u], zt[u])), dt[u]);

    // INV pass 1
    ull s[8];
    idct8p(e, s);
    #pragma unroll
    for (int u = 0; u < 8; u++) *(ull*)(scrf + (u*10 + j)*2) = s[u];
    __syncwarp();
    ull sr[8];
    {
        ulonglong2 u0 = *(const ulonglong2*)(scrf + j*20);
        ulonglong2 u1 = *(const ulonglong2*)(scrf + j*20 + 4);
        ulonglong2 u2 = *(const ulonglong2*)(scrf + j*20 + 8);
        ulonglong2 u3 = *(const ulonglong2*)(scrf + j*20 + 12);
        sr[0]=u0.x; sr[1]=u0.y; sr[2]=u1.x; sr[3]=u1.y;
        sr[4]=u2.x; sr[5]=u2.y; sr[6]=u3.x; sr[7]=u3.y;
    }
    __syncwarp();

    // INV pass 2 (+128 on DC for luma; chroma stays -128)
    if (isY) sr[0] = ADD2(sr[0], BC(128.0f));
    ull p[8];
    idct8p(sr, p);
    {
        float a[8], c[8];
        #pragma unroll
        for (int v = 0; v < 8; v++) UPK2(a[v], c[v], p[v]);
        *(float4*)oA       = make_float4(a[0],a[1],a[2],a[3]);
        *(float4*)(oA + 4) = make_float4(a[4],a[5],a[6],a[7]);
        *(float4*)oB       = make_float4(c[0],c[1],c[2],c[3]);
        *(float4*)(oB + 4) = make_float4(c[4],c[5],c[6],c[7]);
    }
    __syncthreads();

    // ---- YCbCr->RGB, saturate, store (512 tasks) ------------------------
    float* ob = out + (size_t)b * 3 * HH * WW;
    float4* oR = (float4*)ob;
    float4* oG = (float4*)(ob + HH*WW);
    float4* oB4 = (float4*)(ob + 2*HH*WW);
    const float inv255 = 1.0f / 255.0f;

    for (int ti = tid; ti < 512; ti += 192) {
        int py = ti >> 4, c4 = (ti & 15) << 2;
        float4 Y4 = *(float4*)(sY + py*YST + c4);
        float2 CB = *(float2*)(sCbO + (py >> 1)*CST + (c4 >> 1));
        float2 CR = *(float2*)(sCrO + (py >> 1)*CST + (c4 >> 1));
        float yv[4] = {Y4.x, Y4.y, Y4.z, Y4.w};
        float cb[4] = {CB.x, CB.x, CB.y, CB.y};
        float cr[4] = {CR.x, CR.x, CR.y, CR.y};
        float R[4], G[4], Bz[4];
        #pragma unroll
        for (int w = 0; w < 4; w++) {
            float Rv = fmaf(1.402f, cr[w], yv[w]);
            float Gv = fmaf(-0.714136f, cr[w], fmaf(-0.344136f, cb[w], yv[w]));
            float Bv = fmaf(1.772f, cb[w], yv[w]);
            R[w]  = __saturatef(Rv * inv255);
            G[w]  = __saturatef(Gv * inv255);
            Bz[w] = __saturatef(Bv * inv255);
        }
        size_t off = ((size_t)(py0 + py) * WW + px0 + c4) >> 2;
        oR[off]  = make_float4(R[0],R[1],R[2],R[3]);
        oG[off]  = make_float4(G[0],G[1],G[2],G[3]);
        oB4[off] = make_float4(Bz[0],Bz[1],Bz[2],Bz[3]);
    }
}

extern "C" void kernel_launch(void* const* d_in, const int* in_sizes, int n_in,
                              void* d_out, int out_size)
{
    const float* x = (const float*)d_in[0];
    float* y = (float*)d_out;
    int Bn = in_sizes[0] / (3 * HH * WW);
    dim3 grid(WW / 64, HH / 32, Bn);
    djpeg_kernel<<<grid, 192>>>(x, y);
}

// round 13
// speedup vs baseline: 1.2384x; 1.2384x over previous
#include <cuda_runtime.h>
#include <math.h>

#define HH 512
#define WW 512

// cos(k*pi/16)
#define P1 0.980785280403230449f
#define P2 0.923879532511286756f
#define P3 0.831469612302545237f
#define P4 0.707106781186547524f
#define P5 0.555570233019602225f
#define P6 0.382683432365089772f
#define P7 0.195090322016128268f

__constant__ float gQY[64] = {
  16,11,10,16,24,40,51,61,
  12,12,14,19,26,58,60,55,
  14,13,16,24,40,57,69,56,
  14,17,22,29,51,87,80,62,
  18,22,37,56,68,109,103,77,
  24,35,55,64,81,104,113,92,
  49,64,78,87,103,121,120,101,
  72,92,95,98,112,100,103,99
};
__constant__ float gQC[64] = {
  17,18,24,47,99,99,99,99,
  18,21,26,66,99,99,99,99,
  24,26,56,99,99,99,99,99,
  47,66,99,99,99,99,99,99,
  99,99,99,99,99,99,99,99,
  99,99,99,99,99,99,99,99,
  99,99,99,99,99,99,99,99,
  99,99,99,99,99,99,99,99
};

// f[v] = sum_i d[i] * cos((2i+1) v pi/16)   (even/odd butterfly form)
__device__ __forceinline__ void fdct8(const float* d, float* t)
{
    float a0=d[0]+d[7], a1=d[1]+d[6], a2=d[2]+d[5], a3=d[3]+d[4];
    float b0=d[0]-d[7], b1=d[1]-d[6], b2=d[2]-d[5], b3=d[3]-d[4];
    t[0]=(a0+a1)+(a2+a3);
    t[4]=P4*((a0+a3)-(a1+a2));
    t[2]=fmaf(a0,P2, fmaf(a1,P6, fmaf(a2,-P6, -P2*a3)));
    t[6]=fmaf(a0,P6, fmaf(a1,-P2, fmaf(a2,P2, -P6*a3)));
    t[1]=fmaf(b0,P1, fmaf(b1,P3, fmaf(b2,P5,  P7*b3)));
    t[3]=fmaf(b0,P3, fmaf(b1,-P7, fmaf(b2,-P1, -P5*b3)));
    t[5]=fmaf(b0,P5, fmaf(b1,-P1, fmaf(b2,P7,  P3*b3)));
    t[7]=fmaf(b0,P7, fmaf(b1,-P5, fmaf(b2,P3, -P1*b3)));
}

// s[u] = sum_i e[i] * cos((2u+1) i pi/16)   (even/odd butterfly form)
__device__ __forceinline__ void idct8(const float* e, float* s)
{
    float p0 = e[0] + fmaf(e[2],P2,  fmaf(e[4], P4,  P6*e[6]));
    float p1 = e[0] + fmaf(e[2],P6,  fmaf(e[4],-P4, -P2*e[6]));
    float p2 = e[0] + fmaf(e[2],-P6, fmaf(e[4],-P4,  P2*e[6]));
    float p3 = e[0] + fmaf(e[2],-P2, fmaf(e[4], P4, -P6*e[6]));
    float q0 = fmaf(e[1],P1, fmaf(e[3],P3,  fmaf(e[5],P5,  P7*e[7])));
    float q1 = fmaf(e[1],P3, fmaf(e[3],-P7, fmaf(e[5],-P1, -P5*e[7])));
    float q2 = fmaf(e[1],P5, fmaf(e[3],-P1, fmaf(e[5],P7,  P3*e[7])));
    float q3 = fmaf(e[1],P7, fmaf(e[3],-P5, fmaf(e[5],P3, -P1*e[7])));
    s[0]=p0+q0; s[7]=p0-q0;
    s[1]=p1+q1; s[6]=p1-q1;
    s[2]=p2+q2; s[5]=p2-q2;
    s[3]=p3+q3; s[4]=p3-q3;
}

// diff_round(z) = z - (1/pi) * sum_{n=1..9} ((-1)^{n+1}/n) sin(2*pi*n*z)
// Chebyshev-U collapse: sum_n w_n sin(n*th) = sin(th) * P8(cos(th)),
// P8 = sum_n w_n U_{n-1}.  Exact coefficients (verified: P(1)=1/pi, P(-1)=9/pi):
//   c^8: 256/(9pi)      =  9.0541479
//   c^7: -16/pi         = -5.0929582
//   c^6: -2560/(63pi)   = -12.9344970
//   c^5: 56/(3pi)       =  5.9417845
//   c^4: 1936/(105pi)   =  5.8690280
//   c^3: -20/(3pi)      = -2.1220659
//   c^2: -656/(315pi)   = -0.6628930
//   c^1: 0
//   c^0: 263/(315pi)    =  0.2657635
__device__ __forceinline__ float diff_round(float z)
{
    float r  = z - rintf(z);                 // [-0.5, 0.5]
    float h  = r * 3.14159265358979324f;     // half angle in [-pi/2, pi/2]
    float h2 = h * h;

    float sh = h * fmaf(h2, fmaf(h2, fmaf(h2, fmaf(h2, 2.75573192e-6f, -1.98412698e-4f),
                                          8.33333333e-3f), -1.66666667e-1f), 1.0f);
    float ch = fmaf(h2, fmaf(h2, fmaf(h2, fmaf(h2, 2.48015873e-5f, -1.38888889e-3f),
                                      4.16666667e-2f), -5.0e-1f), 1.0f);

    float s1 = (sh + sh) * ch;               // sin(2*pi*r)
    float c  = fmaf(-2.0f * sh, sh, 1.0f);   // cos(2*pi*r)
    float c2 = c * c;

    float p = fmaf(c, 9.0541479f, -5.0929582f);
    p = fmaf(c, p, -12.9344970f);
    p = fmaf(c, p,   5.9417845f);
    p = fmaf(c, p,   5.8690280f);
    p = fmaf(c, p,  -2.1220659f);
    p = fmaf(c, p,  -0.6628930f);
    p = fmaf(c2, p,  0.2657635f);            // covers c^1 (=0) and c^0 in one step

    return z - s1 * p;
}

#define SCR_STRIDE 12    // floats per scratch row (16B-aligned rows)
#define SCR_GROUP  104   // floats per group (8-bank skew between warp groups)

__global__ void __launch_bounds__(192, 8)
djpeg_kernel(const float* __restrict__ in, float* __restrict__ out)
{
    __shared__ __align__(16) float sY  [32*36];       // luma tile, row stride 36
    __shared__ __align__(16) float sCbP[16*20];       // pooled chroma in
    __shared__ __align__(16) float sCrP[16*20];
    __shared__ __align__(16) float sCbO[16*20];       // reconstructed chroma (-128)
    __shared__ __align__(16) float sCrO[16*20];
    __shared__ __align__(16) float sScr[24*SCR_GROUP];// transpose scratch
    __shared__ __align__(16) float sZ[2][64];         // quant multipliers
    __shared__ __align__(16) float sD[2][64];         // dequant multipliers

    const int tid = threadIdx.x;
    const int b   = blockIdx.z;
    const int px0 = blockIdx.x * 32;
    const int py0 = blockIdx.y * 32;

    const float* base = in + (size_t)b * 3 * HH * WW;

    // ---- load (threads 0..127) + tables (threads 128..191) -------------
    if (tid < 128) {
        int rp = tid >> 3;              // row-pair 0..15
        int c4 = (tid & 7) << 2;        // col offset 0,4,...,28
        size_t o0 = ((size_t)(py0 + 2*rp) * WW + px0 + c4) >> 2;
        const float4* R4 = (const float4*)base;
        const float4* G4 = (const float4*)(base + HH*WW);
        const float4* B4 = (const float4*)(base + 2*HH*WW);
        float4 Ra = R4[o0], Rb = R4[o0 + WW/4];
        float4 Ga = G4[o0], Gb = G4[o0 + WW/4];
        float4 Ba = B4[o0], Bb = B4[o0 + WW/4];
        float r0[4]={Ra.x,Ra.y,Ra.z,Ra.w}, r1[4]={Rb.x,Rb.y,Rb.z,Rb.w};
        float g0[4]={Ga.x,Ga.y,Ga.z,Ga.w}, g1[4]={Gb.x,Gb.y,Gb.z,Gb.w};
        float b0[4]={Ba.x,Ba.y,Ba.z,Ba.w}, b1[4]={Bb.x,Bb.y,Bb.z,Bb.w};

        float ya[4], yb[4];
        #pragma unroll
        for (int w = 0; w < 4; w++) {
            ya[w] = fmaf(76.245f, r0[w], fmaf(149.685f, g0[w], 29.07f * b0[w]));
            yb[w] = fmaf(76.245f, r1[w], fmaf(149.685f, g1[w], 29.07f * b1[w]));
        }
        *(float4*)(sY + (2*rp  )*36 + c4) = make_float4(ya[0],ya[1],ya[2],ya[3]);
        *(float4*)(sY + (2*rp+1)*36 + c4) = make_float4(yb[0],yb[1],yb[2],yb[3]);

        float cb[2], cr[2];
        #pragma unroll
        for (int q = 0; q < 2; q++) {
            float rs = (r0[2*q]+r0[2*q+1]) + (r1[2*q]+r1[2*q+1]);
            float gs = (g0[2*q]+g0[2*q+1]) + (g1[2*q]+g1[2*q+1]);
            float bs = (b0[2*q]+b0[2*q+1]) + (b1[2*q]+b1[2*q+1]);
            // 255*0.25*coeff folded; +128 shift included
            cb[q] = fmaf(-10.75692f, rs, fmaf(-21.11808f, gs, fmaf(31.875f,   bs, 128.0f)));
            cr[q] = fmaf( 31.875f,   rs, fmaf(-26.69136f, gs, fmaf(-5.18364f, bs, 128.0f)));
        }
        *(float2*)(sCbP + rp*20 + (tid & 7)*2) = make_float2(cb[0], cb[1]);
        *(float2*)(sCrP + rp*20 + (tid & 7)*2) = make_float2(cr[0], cr[1]);
    } else {
        int i = tid - 128;              // 0..63
        int u = i & 7, v = i >> 3;
        float al = ((u==0)?0.70710678118654752f:1.0f) * ((v==0)?0.70710678118654752f:1.0f);
        float ty = gQY[i], tc = gQC[i];
        sZ[0][i] = 2.5f   * al / ty;    // 0.25*alpha / (T*0.1)
        sD[0][i] = 0.025f * al * ty;    // T*0.1*alpha*0.25
        sZ[1][i] = 2.5f   * al / tc;
        sD[1][i] = 0.025f * al * tc;
    }
    __syncthreads();

    // ---- per-block transforms: groups of 8 threads ----------------------
    const int g = tid >> 3;   // 0..15 Y, 16..19 Cb, 20..23 Cr
    const int j = tid & 7;
    const bool isY = (g < 16);

    const float* srcp;
    float* dstp;
    if (isY) {
        int yr = (g >> 2)*8 + j;
        float* p = sY + yr*36 + (g & 3)*8;
        srcp = p; dstp = p;
    } else {
        int g2 = g & 3;
        int hy = (g2 >> 1)*8 + j, hx0 = (g2 & 1)*8;
        bool isCr = (g >= 20);
        srcp = (isCr ? sCrP : sCbP) + hy*20 + hx0;
        dstp = (isCr ? sCrO : sCbO) + hy*20 + hx0;
    }
    const float* zrow = sZ[isY ? 0 : 1] + j*8;
    const float* drow = sD[isY ? 0 : 1] + j*8;
    float* scr = sScr + g*SCR_GROUP;

    float d[8];
    {
        float4 A = *(const float4*)srcp;
        float4 B = *(const float4*)(srcp + 4);
        d[0]=A.x; d[1]=A.y; d[2]=A.z; d[3]=A.w;
        d[4]=B.x; d[5]=B.y; d[6]=B.z; d[7]=B.w;
    }

    // FWD pass 1 ( -128 level shift folded into DC only )
    float t[8];
    fdct8(d, t);
    t[0] -= 1024.0f;          // == 8 * 128 shift on the DC lane

    #pragma unroll
    for (int v = 0; v < 8; v++) scr[v*SCR_STRIDE + j] = t[v];
    __syncwarp();
    float tr[8];
    {
        float4 A = *(const float4*)(scr + j*SCR_STRIDE);
        float4 B = *(const float4*)(scr + j*SCR_STRIDE + 4);
        tr[0]=A.x; tr[1]=A.y; tr[2]=A.z; tr[3]=A.w;
        tr[4]=B.x; tr[5]=B.y; tr[6]=B.z; tr[7]=B.w;
    }
    __syncwarp();

    // FWD pass 2 + quant + diff_round + dequant
    float t2[8];
    fdct8(tr, t2);
    float e[8];
    #pragma unroll
    for (int u = 0; u < 8; u++)
        e[u] = diff_round(t2[u] * zrow[u]) * drow[u];

    // INV pass 1
    float s[8];
    idct8(e, s);
    #pragma unroll
    for (int u = 0; u < 8; u++) scr[u*SCR_STRIDE + j] = s[u];
    __syncwarp();
    float sr[8];
    {
        float4 A = *(const float4*)(scr + j*SCR_STRIDE);
        float4 B = *(const float4*)(scr + j*SCR_STRIDE + 4);
        sr[0]=A.x; sr[1]=A.y; sr[2]=A.z; sr[3]=A.w;
        sr[4]=B.x; sr[5]=B.y; sr[6]=B.z; sr[7]=B.w;
    }
    __syncwarp();

    // INV pass 2 (+128 folded into DC lane, luma only; chroma stays -128)
    if (isY) sr[0] += 128.0f;
    float p[8];
    idct8(sr, p);
    *(float4*)dstp       = make_float4(p[0],p[1],p[2],p[3]);
    *(float4*)(dstp + 4) = make_float4(p[4],p[5],p[6],p[7]);

    __syncthreads();

    // ---- YCbCr->RGB with 1/255 folded, saturate, store -------------------
    float* ob = out + (size_t)b * 3 * HH * WW;
    float4* oR = (float4*)ob;
    float4* oG = (float4*)(ob + HH*WW);
    float4* oB = (float4*)(ob + 2*HH*WW);

    #pragma unroll
    for (int it = 0; it < 2; it++) {
        int ti = tid + it*192;
        if (ti < 256) {
            int py = ti >> 3, c4 = (ti & 7) << 2;
            float4 Y4 = *(float4*)(sY + py*36 + c4);
            float2 CB = *(float2*)(sCbO + (py >> 1)*20 + (c4 >> 1));
            float2 CR = *(float2*)(sCrO + (py >> 1)*20 + (c4 >> 1));
            float yv[4] = {Y4.x, Y4.y, Y4.z, Y4.w};
            float cb[4] = {CB.x, CB.x, CB.y, CB.y};
            float cr[4] = {CR.x, CR.x, CR.y, CR.y};
            float R[4], G[4], Bz[4];
            #pragma unroll
            for (int w = 0; w < 4; w++) {
                float yn = yv[w] * 0.0039215686f;                    // y/255
                R[w]  = __saturatef(fmaf(cr[w],  0.0054980392f, yn));
                G[w]  = __saturatef(fmaf(cr[w], -0.0028005333f,
                                    fmaf(cb[w], -0.0013495529f, yn)));
                Bz[w] = __saturatef(fmaf(cb[w],  0.0069490196f, yn));
            }
            size_t off = ((size_t)(py0 + py) * WW + px0 + c4) >> 2;
            oR[off] = make_float4(R[0],R[1],R[2],R[3]);
            oG[off] = make_float4(G[0],G[1],G[2],G[3]);
            oB[off] = make_float4(Bz[0],Bz[1],Bz[2],Bz[3]);
        }
    }
}

extern "C" void kernel_launch(void* const* d_in, const int* in_sizes, int n_in,
                              void* d_out, int out_size)
{
    const float* x = (const float*)d_in[0];
    float* y = (float*)d_out;
    int Bn = in_sizes[0] / (3 * HH * WW);
    dim3 grid(WW / 32, HH / 32, Bn);
    djpeg_kernel<<<grid, 192>>>(x, y);
}